// round 15
// baseline (speedup 1.0000x reference)
#include <cuda_runtime.h>
#include <math.h>
#include <stdint.h>
#include <mma.h>

using namespace nvcuda;

#define Bdim 64
#define Tdim 512
#define Idim 256
#define Hdim 512
#define BH   (Bdim*Hdim)   // 32768

// Scratch (device globals: no allocations allowed)
__device__ float g_xw0[(size_t)Tdim*Bdim*Hdim];  // layer-0 input projection
__device__ float g_h0 [(size_t)Tdim*Bdim*Hdim];  // layer-0 hidden states
__device__ float g_h1 [(size_t)Tdim*Bdim*Hdim];  // layer-1 hidden states
__device__ int   g_flag[2][8][32][32];           // scan step flags, one 128B line each

__global__ void zero_flags_k() {
    int i = blockIdx.x * blockDim.x + threadIdx.x;
    if (i < 2 * 8 * 32 * 32) ((int*)g_flag)[i] = 0;
}

__device__ __forceinline__ void st_release_gpu(int* p, int v) {
    asm volatile("st.release.gpu.u32 [%0], %1;" :: "l"(p), "r"(v) : "memory");
}
__device__ __forceinline__ int ld_acquire_gpu(const int* p) {
    int v;
    asm volatile("ld.acquire.gpu.u32 %0, [%1];" : "=r"(v) : "l"(p) : "memory");
    return v;
}

// ---------------------------------------------------------------------------
// 3xTF32 tensor-core projection GEMM for layer 0 (proven R11 kernel).
// g_xw0[m][n] = sum_k x[m][k] * Wih0[n][k] + bih0[n] + bhh0[n]
// ---------------------------------------------------------------------------
#define LDA 36
#define A_FL (128 * LDA)
#define B_FL (64 * LDA)
#define BUF_FL (2 * (A_FL + B_FL))
#define TOT_FL (2 * BUF_FL)          // 110592 B
#define LDC 72

__global__ __launch_bounds__(256, 2) void proj_tc(
    const float* __restrict__ xin, const float* __restrict__ W,
    const float* __restrict__ b1,  const float* __restrict__ b2)
{
    extern __shared__ float s[];
    __shared__ float biasS[64];
    const int KD = Idim;

    const int tid = threadIdx.x;
    const int wid = tid >> 5;
    const int n0 = blockIdx.x * 64;
    const int m0 = blockIdx.y * 128;
    const int wm = wid & 3;
    const int wn = wid >> 2;

    if (tid < 64) biasS[tid] = b1[n0 + tid] + b2[n0 + tid];

    int a_row[4], a_col[4];
    #pragma unroll
    for (int i = 0; i < 4; i++) {
        int idx = tid + i * 256;
        a_row[i] = idx >> 3;
        a_col[i] = (idx & 7) * 4;
    }
    int b_row[2], b_col[2];
    #pragma unroll
    for (int i = 0; i < 2; i++) {
        int idx = tid + i * 256;
        b_row[i] = idx >> 3;
        b_col[i] = (idx & 7) * 4;
    }

    size_t a_off[4];
    #pragma unroll
    for (int i = 0; i < 4; i++) {
        int m = m0 + a_row[i];
        a_off[i] = ((size_t)(m & 63) * Tdim + (m >> 6)) * KD;   // x is [B,T,I]
    }
    size_t b_off[2];
    #pragma unroll
    for (int i = 0; i < 2; i++)
        b_off[i] = (size_t)(n0 + b_row[i]) * KD;

    wmma::fragment<wmma::accumulator, 16, 16, 8, float> cf[2][2];
    #pragma unroll
    for (int i = 0; i < 2; i++)
        #pragma unroll
        for (int j = 0; j < 2; j++)
            wmma::fill_fragment(cf[i][j], 0.0f);

    float4 pa[4], pb[2];

    auto stage = [&](float* base) {
        float* Ah = base;
        float* Al = base + A_FL;
        float* Bh = base + 2 * A_FL;
        float* Bl = base + 2 * A_FL + B_FL;
        #pragma unroll
        for (int i = 0; i < 4; i++) {
            int o = a_row[i] * LDA + a_col[i];
            float hx = wmma::__float_to_tf32(pa[i].x);
            float hy = wmma::__float_to_tf32(pa[i].y);
            float hz = wmma::__float_to_tf32(pa[i].z);
            float hw = wmma::__float_to_tf32(pa[i].w);
            Ah[o+0] = hx; Ah[o+1] = hy; Ah[o+2] = hz; Ah[o+3] = hw;
            Al[o+0] = pa[i].x - hx; Al[o+1] = pa[i].y - hy;
            Al[o+2] = pa[i].z - hz; Al[o+3] = pa[i].w - hw;
        }
        #pragma unroll
        for (int i = 0; i < 2; i++) {
            int o = b_row[i] * LDA + b_col[i];
            float hx = wmma::__float_to_tf32(pb[i].x);
            float hy = wmma::__float_to_tf32(pb[i].y);
            float hz = wmma::__float_to_tf32(pb[i].z);
            float hw = wmma::__float_to_tf32(pb[i].w);
            Bh[o+0] = hx; Bh[o+1] = hy; Bh[o+2] = hz; Bh[o+3] = hw;
            Bl[o+0] = pb[i].x - hx; Bl[o+1] = pb[i].y - hy;
            Bl[o+2] = pb[i].z - hz; Bl[o+3] = pb[i].w - hw;
        }
    };
    auto gload = [&](int kt) {
        int k0 = kt * 32;
        #pragma unroll
        for (int i = 0; i < 4; i++)
            pa[i] = *reinterpret_cast<const float4*>(xin + a_off[i] + k0 + a_col[i]);
        #pragma unroll
        for (int i = 0; i < 2; i++)
            pb[i] = *reinterpret_cast<const float4*>(W + b_off[i] + k0 + b_col[i]);
    };

    const int KT = KD / 32;
    gload(0);
    stage(s);
    if (KT > 1) gload(1);
    __syncthreads();

    for (int kt = 0; kt < KT; ++kt) {
        float* cur = s + (kt & 1) * BUF_FL;
        if (kt + 1 < KT) stage(s + ((kt + 1) & 1) * BUF_FL);

        const float* Ah = cur;
        const float* Al = cur + A_FL;
        const float* Bh = cur + 2 * A_FL;
        const float* Bl = cur + 2 * A_FL + B_FL;
        #pragma unroll
        for (int kk = 0; kk < 32; kk += 8) {
            wmma::fragment<wmma::matrix_a, 16, 16, 8, wmma::precision::tf32, wmma::row_major> ah[2], al[2];
            wmma::fragment<wmma::matrix_b, 16, 16, 8, wmma::precision::tf32, wmma::col_major> bh[2], bl[2];
            #pragma unroll
            for (int i = 0; i < 2; i++) {
                wmma::load_matrix_sync(ah[i], Ah + (wm * 32 + i * 16) * LDA + kk, LDA);
                wmma::load_matrix_sync(al[i], Al + (wm * 32 + i * 16) * LDA + kk, LDA);
            }
            #pragma unroll
            for (int j = 0; j < 2; j++) {
                wmma::load_matrix_sync(bh[j], Bh + (wn * 32 + j * 16) * LDA + kk, LDA);
                wmma::load_matrix_sync(bl[j], Bl + (wn * 32 + j * 16) * LDA + kk, LDA);
            }
            #pragma unroll
            for (int i = 0; i < 2; i++)
                #pragma unroll
                for (int j = 0; j < 2; j++) {
                    wmma::mma_sync(cf[i][j], al[i], bh[j], cf[i][j]);
                    wmma::mma_sync(cf[i][j], ah[i], bl[j], cf[i][j]);
                    wmma::mma_sync(cf[i][j], ah[i], bh[j], cf[i][j]);
                }
        }
        if (kt + 2 < KT) gload(kt + 2);
        __syncthreads();
    }

    #pragma unroll
    for (int i = 0; i < 2; i++)
        #pragma unroll
        for (int j = 0; j < 2; j++)
            wmma::store_matrix_sync(s + (wm * 32 + i * 16) * LDC + wn * 32 + j * 16,
                                    cf[i][j], LDC, wmma::mem_row_major);
    __syncthreads();

    #pragma unroll
    for (int i = 0; i < 8; i++) {
        int idx = tid + i * 256;
        int row = idx >> 4;
        int col = (idx & 15) * 4;
        float4 o;
        o.x = s[row * LDC + col + 0] + biasS[col + 0];
        o.y = s[row * LDC + col + 1] + biasS[col + 1];
        o.z = s[row * LDC + col + 2] + biasS[col + 2];
        o.w = s[row * LDC + col + 3] + biasS[col + 3];
        *reinterpret_cast<float4*>(&g_xw0[(size_t)(m0 + row) * Hdim + n0 + col]) = o;
    }
}

// ---------------------------------------------------------------------------
// Fused dual-layer scan, forward-dependency-safe (single kernel, no PDL).
// Grid (16 jblk, 8 bblk, 2 layer) = 256 CTAs, ALL co-resident (2/SM):
//   regs <= 128 (launch_bounds), dyn smem 107008 B/CTA -> 214 KB/SM < 228 KB.
// Layer 0: h0[t] = relu(xw0[t] + h0[t-1] @ Whh0^T)   (xw0 precomputed).
// Layer 1: h1[t] = relu(bih1+bhh1 + h0[t] @ Wih1^T + h1[t-1] @ Whh1^T),
//   the Wih1 matvec computed INLINE (slice cached in smem, stride 516 floats
//   = 129 float4 == 1 mod 8 -> conflict-free LDS.128). Layer-1 waits only on
//   layer-0 flags (co-resident peers) and its own chain -> deadlock-free.
// ---------------------------------------------------------------------------
#define WIS_FL   (32 * 516)            // 16512 floats (Wih1 slice, padded rows)
#define SC_HS0   WIS_FL                // 4096 floats
#define SC_HS1   (WIS_FL + 4096)
#define SC_PART  (WIS_FL + 8192)       // 2048 floats
#define SC_TOT_B ((WIS_FL + 8192 + 2048) * 4)   // 107008 B

__global__ __launch_bounds__(256, 2) void rnn_scan2(
    const float* __restrict__ Whh0, const float* __restrict__ Whh1,
    const float* __restrict__ Wih1,
    const float* __restrict__ bih1, const float* __restrict__ bhh1)
{
    extern __shared__ float dyn[];
    float* Wis  = dyn;
    float* hs0  = dyn + SC_HS0;
    float* hs1  = dyn + SC_HS1;
    float* part = dyn + SC_PART;

    const int tid  = threadIdx.x;
    const int w    = tid >> 5;
    const int lane = tid & 31;
    const int jblk = blockIdx.x;
    const int bblk = blockIdx.y;
    const int layer = blockIdx.z;
    const int j = jblk * 32 + lane;
    const int rowbase = bblk * 8;
    int* myflag = &g_flag[layer][bblk][jblk][0];
    // Poll set: lanes 0-1 -> own-layer producers; lanes 2-3 -> layer-0 (layer 1 only)
    const int* pf_own = (lane < 2) ? &g_flag[layer][bblk][2 * w + lane][0] : nullptr;
    const int* pf_l0  = (layer == 1 && lane >= 2 && lane < 4)
                        ? &g_flag[0][bblk][2 * w + (lane - 2)][0] : nullptr;

    const float* __restrict__ Whh = layer ? Whh1 : Whh0;
    float* __restrict__ hbuf      = layer ? g_h1 : g_h0;

    // Weight-stationary Whh slice: Whh[j][w*64 .. w*64+63]
    float4 wv[16];
    const float4* Wr = reinterpret_cast<const float4*>(Whh + (size_t)j * Hdim + w * 64);
    #pragma unroll
    for (int i = 0; i < 16; i++) wv[i] = Wr[i];

    const int b2 = tid >> 5, j2 = tid & 31;
    const size_t outbase = (size_t)(rowbase + b2) * Hdim + jblk * 32 + j2;

    float bias1 = 0.f;
    if (layer == 1) {
        // Cache Wih1 slice: rows j=jblk*32+r (r 0..31), 512 floats, padded stride 516
        float4* Wis4 = reinterpret_cast<float4*>(Wis);
        for (int idx = tid; idx < 32 * 128; idx += 256) {
            int r = idx >> 7, q = idx & 127;
            Wis4[r * 129 + q] = reinterpret_cast<const float4*>(
                Wih1 + (size_t)(jblk * 32 + r) * Hdim)[q];
        }
        int jj = jblk * 32 + j2;
        bias1 = bih1[jj] + bhh1[jj];
    }
    __syncthreads();

    float4* hs0_4 = reinterpret_cast<float4*>(hs0);
    float4* hs1_4 = reinterpret_cast<float4*>(hs1);
    const float4* Wis4c = reinterpret_cast<const float4*>(Wis);

    int l_b[4], l_q[4];
    #pragma unroll
    for (int i = 0; i < 4; i++) {
        int idx = lane + i * 32;
        l_b[i] = idx >> 4;
        l_q[i] = idx & 15;
    }

    for (int t = 0; t < Tdim; ++t) {
        const size_t off = (size_t)t * BH + outbase;
        float acc[8];
        #pragma unroll
        for (int b = 0; b < 8; b++) acc[b] = 0.f;

        if (layer == 0) {
            float xv = __ldcg(&g_xw0[off]);   // prefetch before wait

            if (t > 0) {
                for (;;) {
                    int v = (lane < 2) ? ld_acquire_gpu(pf_own) : 0x7fffffff;
                    if (__all_sync(0xffffffffu, v >= t)) break;
                }
                const float4* src = reinterpret_cast<const float4*>(
                    g_h0 + (size_t)(t - 1) * BH + (size_t)rowbase * Hdim);
                #pragma unroll
                for (int i = 0; i < 4; i++)
                    hs0_4[l_b[i] * 128 + w * 16 + l_q[i]] =
                        __ldcg(&src[l_b[i] * 128 + w * 16 + l_q[i]]);
            } else {
                float4 z = make_float4(0.f, 0.f, 0.f, 0.f);
                #pragma unroll
                for (int i = 0; i < 4; i++)
                    hs0_4[l_b[i] * 128 + w * 16 + l_q[i]] = z;
            }
            __syncwarp();

            #pragma unroll
            for (int i = 0; i < 16; i++) {
                float4 w4 = wv[i];
                #pragma unroll
                for (int b = 0; b < 8; b++) {
                    float4 h4 = hs0_4[b * 128 + w * 16 + i];
                    acc[b] = fmaf(h4.w, w4.w,
                              fmaf(h4.z, w4.z,
                               fmaf(h4.y, w4.y,
                                fmaf(h4.x, w4.x, acc[b]))));
                }
            }
            #pragma unroll
            for (int b = 0; b < 8; b++)
                part[(w * 8 + b) * 32 + lane] = acc[b];
            __syncthreads();

            float s2 = 0.f;
            #pragma unroll
            for (int ww = 0; ww < 8; ww++)
                s2 += part[(ww * 8 + b2) * 32 + j2];
            g_h0[off] = fmaxf(xv + s2, 0.f);
            __syncthreads();
            if (tid == 0) st_release_gpu(myflag, t + 1);
        } else {
            // Wait: own flags >= t (h1[t-1]) AND layer-0 flags >= t+1 (h0[t])
            {
                int tgt_own = t, tgt_l0 = t + 1;
                for (;;) {
                    int v = 0x7fffffff;
                    if (lane < 2) { if (t > 0) v = ld_acquire_gpu(pf_own) - tgt_own; else v = 0; }
                    else if (lane < 4) v = ld_acquire_gpu(pf_l0) - tgt_l0;
                    if (__all_sync(0xffffffffu, v >= 0)) break;
                }
            }
            // Load h0[t] slice
            {
                const float4* src = reinterpret_cast<const float4*>(
                    g_h0 + (size_t)t * BH + (size_t)rowbase * Hdim);
                #pragma unroll
                for (int i = 0; i < 4; i++)
                    hs0_4[l_b[i] * 128 + w * 16 + l_q[i]] =
                        __ldcg(&src[l_b[i] * 128 + w * 16 + l_q[i]]);
            }
            // Load h1[t-1] slice (zeros at t=0)
            if (t > 0) {
                const float4* src = reinterpret_cast<const float4*>(
                    g_h1 + (size_t)(t - 1) * BH + (size_t)rowbase * Hdim);
                #pragma unroll
                for (int i = 0; i < 4; i++)
                    hs1_4[l_b[i] * 128 + w * 16 + l_q[i]] =
                        __ldcg(&src[l_b[i] * 128 + w * 16 + l_q[i]]);
            } else {
                float4 z = make_float4(0.f, 0.f, 0.f, 0.f);
                #pragma unroll
                for (int i = 0; i < 4; i++)
                    hs1_4[l_b[i] * 128 + w * 16 + l_q[i]] = z;
            }
            __syncwarp();

            // Matvec 1: h1[t-1] @ Whh1^T (weights in registers)
            #pragma unroll
            for (int i = 0; i < 16; i++) {
                float4 w4 = wv[i];
                #pragma unroll
                for (int b = 0; b < 8; b++) {
                    float4 h4 = hs1_4[b * 128 + w * 16 + i];
                    acc[b] = fmaf(h4.w, w4.w,
                              fmaf(h4.z, w4.z,
                               fmaf(h4.y, w4.y,
                                fmaf(h4.x, w4.x, acc[b]))));
                }
            }
            // Matvec 2: h0[t] @ Wih1^T (weights from smem, conflict-free)
            #pragma unroll
            for (int i = 0; i < 16; i++) {
                float4 w4 = Wis4c[lane * 129 + w * 16 + i];
                #pragma unroll
                for (int b = 0; b < 8; b++) {
                    float4 h4 = hs0_4[b * 128 + w * 16 + i];
                    acc[b] = fmaf(h4.w, w4.w,
                              fmaf(h4.z, w4.z,
                               fmaf(h4.y, w4.y,
                                fmaf(h4.x, w4.x, acc[b]))));
                }
            }
            #pragma unroll
            for (int b = 0; b < 8; b++)
                part[(w * 8 + b) * 32 + lane] = acc[b];
            __syncthreads();

            float s2 = 0.f;
            #pragma unroll
            for (int ww = 0; ww < 8; ww++)
                s2 += part[(ww * 8 + b2) * 32 + j2];
            g_h1[off] = fmaxf(bias1 + s2, 0.f);
            __syncthreads();
            if (tid == 0) st_release_gpu(myflag, t + 1);
        }
    }
}

// ---------------------------------------------------------------------------
// FC + sigmoid: out[b*T + t] = sigmoid(dot(h1[t][b], W_fc) + b_fc)
// ---------------------------------------------------------------------------
__global__ __launch_bounds__(256) void fc_sigmoid(
    const float* __restrict__ wfc, const float* __restrict__ bfc,
    float* __restrict__ out)
{
    int gw   = (blockIdx.x * blockDim.x + threadIdx.x) >> 5;
    int lane = threadIdx.x & 31;
    int t = gw >> 6, b = gw & 63;

    const float4* hp = reinterpret_cast<const float4*>(g_h1 + (size_t)gw * Hdim);
    const float4* wp = reinterpret_cast<const float4*>(wfc);
    float s = 0.f;
    #pragma unroll
    for (int r = 0; r < 4; r++) {
        float4 hv = hp[lane + r * 32];
        float4 wv = wp[lane + r * 32];
        s += hv.x * wv.x + hv.y * wv.y + hv.z * wv.z + hv.w * wv.w;
    }
    #pragma unroll
    for (int o = 16; o > 0; o >>= 1)
        s += __shfl_xor_sync(0xffffffffu, s, o);
    if (lane == 0) {
        float v = s + bfc[0];
        out[(size_t)b * Tdim + t] = 1.f / (1.f + expf(-v));
    }
}

// ---------------------------------------------------------------------------
extern "C" void kernel_launch(void* const* d_in, const int* in_sizes, int n_in,
                              void* d_out, int out_size)
{
    (void)in_sizes; (void)n_in; (void)out_size;
    const float* x    = (const float*)d_in[0];
    const float* Wih0 = (const float*)d_in[1];
    const float* Whh0 = (const float*)d_in[2];
    const float* bih0 = (const float*)d_in[3];
    const float* bhh0 = (const float*)d_in[4];
    const float* Wih1 = (const float*)d_in[5];
    const float* Whh1 = (const float*)d_in[6];
    const float* bih1 = (const float*)d_in[7];
    const float* bhh1 = (const float*)d_in[8];
    const float* Wfc  = (const float*)d_in[9];
    const float* bfc  = (const float*)d_in[10];
    float* out = (float*)d_out;

    const int proj_smem = TOT_FL * sizeof(float);   // 110592 B
    static bool attr_set = false;
    if (!attr_set) {
        cudaFuncSetAttribute(proj_tc,
                             cudaFuncAttributeMaxDynamicSharedMemorySize, proj_smem);
        cudaFuncSetAttribute(rnn_scan2,
                             cudaFuncAttributeMaxDynamicSharedMemorySize, SC_TOT_B);
        attr_set = true;
    }

    dim3 gemm_grid(8, 256);
    dim3 scan_grid(16, 8, 2);

    // Plain serial schedule, forward dependencies only. No PDL.
    zero_flags_k<<<32, 512>>>();
    proj_tc<<<gemm_grid, 256, proj_smem>>>(x, Wih0, bih0, bhh0);
    rnn_scan2<<<scan_grid, 256, SC_TOT_B>>>(Whh0, Whh1, Wih1, bih1, bhh1);
    fc_sigmoid<<<4096, 256>>>(Wfc, bfc, out);
}

// round 16
// speedup vs baseline: 1.0939x; 1.0939x over previous
#include <cuda_runtime.h>
#include <math.h>
#include <stdint.h>
#include <mma.h>

using namespace nvcuda;

#define Bdim 64
#define Tdim 512
#define Idim 256
#define Hdim 512
#define BH   (Bdim*Hdim)   // 32768

// Scratch (device globals: no allocations allowed)
__device__ float g_xw0[(size_t)Tdim*Bdim*Hdim];  // layer-0 input projection
__device__ float g_xw1[(size_t)Tdim*Bdim*Hdim];  // layer-1 input projection
__device__ float g_h0 [(size_t)Tdim*Bdim*Hdim];  // layer-0 hidden states
__device__ float g_h1 [(size_t)Tdim*Bdim*Hdim];  // layer-1 hidden states
__device__ int   g_flag[2][8][32][32];           // scan step flags, one 128B line each
__device__ int   g_pdone[2][256][32];            // proj per-(layer,by) done counters (8 = all bx)

__global__ void zero_flags_k() {
    int i = blockIdx.x * blockDim.x + threadIdx.x;
    if (i < 2 * 8 * 32 * 32) ((int*)g_flag)[i] = 0;
    if (i < 2 * 256 * 32) ((int*)g_pdone)[i] = 0;
}

__device__ __forceinline__ void st_release_gpu(int* p, int v) {
    asm volatile("st.release.gpu.u32 [%0], %1;" :: "l"(p), "r"(v) : "memory");
}
__device__ __forceinline__ int ld_acquire_gpu(const int* p) {
    int v;
    asm volatile("ld.acquire.gpu.u32 %0, [%1];" : "=r"(v) : "l"(p) : "memory");
    return v;
}
__device__ __forceinline__ void red_add_release_gpu(int* p, int v) {
    asm volatile("red.release.gpu.global.add.u32 [%0], %1;" :: "l"(p), "r"(v) : "memory");
}

// ---------------------------------------------------------------------------
// 3xTF32 tensor-core projection GEMM (near-fp32 accuracy), double-buffered.
// out[m][n] = sum_k A[m][k] * W[n][k] + b1[n] + b2[n]
// FIRST: A = x [B,T,I], out = g_xw0; triggers PDL at entry (never waits ->
//   guaranteed progress; scan0 mounts beside/after it and gates on g_pdone).
// else : A = g_h0, out = g_xw1; gated per-by on layer-0 scan flags (R12 path);
//   NO early trigger (scan1 must wait for proj1 completion -- R13 lesson).
// Both release g_pdone[layer][by] after their tile stores.
// ---------------------------------------------------------------------------
#define LDA 36
#define A_FL (128 * LDA)
#define B_FL (64 * LDA)
#define BUF_FL (2 * (A_FL + B_FL))
#define TOT_FL (2 * BUF_FL)          // 110592 B
#define LDC 72

template<int KD, bool FIRST>
__global__ __launch_bounds__(256, 2) void proj_tc(
    const float* __restrict__ xin, const float* __restrict__ W,
    const float* __restrict__ b1,  const float* __restrict__ b2)
{
    extern __shared__ float s[];
    __shared__ float biasS[64];

    if (FIRST && threadIdx.x == 0) cudaTriggerProgrammaticLaunchCompletion();

    const float* __restrict__ A = FIRST ? xin : (const float*)g_h0;
    float* __restrict__ outp = FIRST ? g_xw0 : g_xw1;
    const int tid = threadIdx.x;
    const int wid = tid >> 5;
    const int lane = tid & 31;
    const int n0 = blockIdx.x * 64;
    const int m0 = blockIdx.y * 128;
    const int wm = wid & 3;
    const int wn = wid >> 2;

    if (!FIRST) {
        // Need h0 rows for t = 2by, 2by+1: all 128 (bblk,jblk) flags >= 2by+2
        if (wid == 0) {
            const int target = 2 * (int)blockIdx.y + 2;
            for (;;) {
                int ok = 1;
                #pragma unroll
                for (int q = 0; q < 4; q++) {
                    int idx = lane + q * 32;
                    int v = ld_acquire_gpu(&g_flag[0][idx >> 4][idx & 15][0]);
                    ok &= (v >= target);
                }
                if (__all_sync(0xffffffffu, ok)) break;
                __nanosleep(256);
            }
        }
        __syncthreads();
    }

    if (tid < 64) biasS[tid] = b1[n0 + tid] + b2[n0 + tid];

    int a_row[4], a_col[4];
    #pragma unroll
    for (int i = 0; i < 4; i++) {
        int idx = tid + i * 256;
        a_row[i] = idx >> 3;
        a_col[i] = (idx & 7) * 4;
    }
    int b_row[2], b_col[2];
    #pragma unroll
    for (int i = 0; i < 2; i++) {
        int idx = tid + i * 256;
        b_row[i] = idx >> 3;
        b_col[i] = (idx & 7) * 4;
    }

    size_t a_off[4];
    #pragma unroll
    for (int i = 0; i < 4; i++) {
        int m = m0 + a_row[i];
        a_off[i] = FIRST ? ((size_t)(m & 63) * Tdim + (m >> 6)) * KD
                         : (size_t)m * KD;
    }
    size_t b_off[2];
    #pragma unroll
    for (int i = 0; i < 2; i++)
        b_off[i] = (size_t)(n0 + b_row[i]) * KD;

    wmma::fragment<wmma::accumulator, 16, 16, 8, float> cf[2][2];
    #pragma unroll
    for (int i = 0; i < 2; i++)
        #pragma unroll
        for (int j = 0; j < 2; j++)
            wmma::fill_fragment(cf[i][j], 0.0f);

    float4 pa[4], pb[2];

    auto stage = [&](float* base) {
        float* Ah = base;
        float* Al = base + A_FL;
        float* Bh = base + 2 * A_FL;
        float* Bl = base + 2 * A_FL + B_FL;
        #pragma unroll
        for (int i = 0; i < 4; i++) {
            int o = a_row[i] * LDA + a_col[i];
            float hx = wmma::__float_to_tf32(pa[i].x);
            float hy = wmma::__float_to_tf32(pa[i].y);
            float hz = wmma::__float_to_tf32(pa[i].z);
            float hw = wmma::__float_to_tf32(pa[i].w);
            Ah[o+0] = hx; Ah[o+1] = hy; Ah[o+2] = hz; Ah[o+3] = hw;
            Al[o+0] = pa[i].x - hx; Al[o+1] = pa[i].y - hy;
            Al[o+2] = pa[i].z - hz; Al[o+3] = pa[i].w - hw;
        }
        #pragma unroll
        for (int i = 0; i < 2; i++) {
            int o = b_row[i] * LDA + b_col[i];
            float hx = wmma::__float_to_tf32(pb[i].x);
            float hy = wmma::__float_to_tf32(pb[i].y);
            float hz = wmma::__float_to_tf32(pb[i].z);
            float hw = wmma::__float_to_tf32(pb[i].w);
            Bh[o+0] = hx; Bh[o+1] = hy; Bh[o+2] = hz; Bh[o+3] = hw;
            Bl[o+0] = pb[i].x - hx; Bl[o+1] = pb[i].y - hy;
            Bl[o+2] = pb[i].z - hz; Bl[o+3] = pb[i].w - hw;
        }
    };
    auto gload = [&](int kt) {
        int k0 = kt * 32;
        #pragma unroll
        for (int i = 0; i < 4; i++)
            pa[i] = *reinterpret_cast<const float4*>(A + a_off[i] + k0 + a_col[i]);
        #pragma unroll
        for (int i = 0; i < 2; i++)
            pb[i] = *reinterpret_cast<const float4*>(W + b_off[i] + k0 + b_col[i]);
    };

    const int KT = KD / 32;
    gload(0);
    stage(s);
    if (KT > 1) gload(1);
    __syncthreads();

    for (int kt = 0; kt < KT; ++kt) {
        float* cur = s + (kt & 1) * BUF_FL;
        if (kt + 1 < KT) stage(s + ((kt + 1) & 1) * BUF_FL);

        const float* Ah = cur;
        const float* Al = cur + A_FL;
        const float* Bh = cur + 2 * A_FL;
        const float* Bl = cur + 2 * A_FL + B_FL;
        #pragma unroll
        for (int kk = 0; kk < 32; kk += 8) {
            wmma::fragment<wmma::matrix_a, 16, 16, 8, wmma::precision::tf32, wmma::row_major> ah[2], al[2];
            wmma::fragment<wmma::matrix_b, 16, 16, 8, wmma::precision::tf32, wmma::col_major> bh[2], bl[2];
            #pragma unroll
            for (int i = 0; i < 2; i++) {
                wmma::load_matrix_sync(ah[i], Ah + (wm * 32 + i * 16) * LDA + kk, LDA);
                wmma::load_matrix_sync(al[i], Al + (wm * 32 + i * 16) * LDA + kk, LDA);
            }
            #pragma unroll
            for (int j = 0; j < 2; j++) {
                wmma::load_matrix_sync(bh[j], Bh + (wn * 32 + j * 16) * LDA + kk, LDA);
                wmma::load_matrix_sync(bl[j], Bl + (wn * 32 + j * 16) * LDA + kk, LDA);
            }
            #pragma unroll
            for (int i = 0; i < 2; i++)
                #pragma unroll
                for (int j = 0; j < 2; j++) {
                    wmma::mma_sync(cf[i][j], al[i], bh[j], cf[i][j]);
                    wmma::mma_sync(cf[i][j], ah[i], bl[j], cf[i][j]);
                    wmma::mma_sync(cf[i][j], ah[i], bh[j], cf[i][j]);
                }
        }
        if (kt + 2 < KT) gload(kt + 2);
        __syncthreads();
    }

    #pragma unroll
    for (int i = 0; i < 2; i++)
        #pragma unroll
        for (int j = 0; j < 2; j++)
            wmma::store_matrix_sync(s + (wm * 32 + i * 16) * LDC + wn * 32 + j * 16,
                                    cf[i][j], LDC, wmma::mem_row_major);
    __syncthreads();

    #pragma unroll
    for (int i = 0; i < 8; i++) {
        int idx = tid + i * 256;
        int row = idx >> 4;
        int col = (idx & 15) * 4;
        float4 o;
        o.x = s[row * LDC + col + 0] + biasS[col + 0];
        o.y = s[row * LDC + col + 1] + biasS[col + 1];
        o.z = s[row * LDC + col + 2] + biasS[col + 2];
        o.w = s[row * LDC + col + 3] + biasS[col + 3];
        *reinterpret_cast<float4*>(&outp[(size_t)(m0 + row) * Hdim + n0 + col]) = o;
    }
    __syncthreads();   // all tile stores done
    if (tid == 0) red_add_release_gpu(&g_pdone[FIRST ? 0 : 1][blockIdx.y][0], 1);
}

// ---------------------------------------------------------------------------
// Recurrent scan (R8 sync design + per-by projection gate).
// Grid (16 jblk, 8 bblk), 256 threads, <=128 regs (2 CTAs/SM budget).
// Each step t gates on g_pdone[layer][t>>1] == 8 (per-warp cached) before
// touching xw -- forward dep (proj launched earlier). Triggers PDL at entry
// so the NEXT PDL launch (proj1 after scan0) can come up.
// ---------------------------------------------------------------------------
__global__ __launch_bounds__(256, 2) void rnn_scan(const float* __restrict__ Whh, int layer)
{
    if (threadIdx.x == 0) cudaTriggerProgrammaticLaunchCompletion();

    __shared__ __align__(16) float hs[8 * 512];
    __shared__ __align__(16) float part[8 * 8 * 32];

    const int tid  = threadIdx.x;
    const int w    = tid >> 5;
    const int lane = tid & 31;
    const int jblk = blockIdx.x;
    const int bblk = blockIdx.y;
    const int j = jblk * 32 + lane;
    const int rowbase = bblk * 8;
    const float* __restrict__ xw = layer ? g_xw1 : g_xw0;
    float* __restrict__ hbuf     = layer ? g_h1  : g_h0;
    int* myflag = &g_flag[layer][bblk][jblk][0];
    const int* pf = (lane < 2) ? &g_flag[layer][bblk][2 * w + lane][0] : nullptr;

    float4 wv[16];
    const float4* Wr = reinterpret_cast<const float4*>(Whh + (size_t)j * Hdim + w * 64);
    #pragma unroll
    for (int i = 0; i < 16; i++) wv[i] = Wr[i];

    float4* hs4 = reinterpret_cast<float4*>(hs);
    const int b2 = tid >> 5, j2 = tid & 31;
    const size_t outbase = (size_t)(rowbase + b2) * Hdim + jblk * 32 + j2;

    int l_b[4], l_q[4];
    #pragma unroll
    for (int i = 0; i < 4; i++) {
        int idx = lane + i * 32;
        l_b[i] = idx >> 4;
        l_q[i] = idx & 15;
    }

    int by_ready = 0;   // highest by known complete (per-warp cached)

    for (int t = 0; t < Tdim; ++t) {
        // Gate on the projection tile that owns xw[t]
        const int by = t >> 1;
        if (by_ready <= by) {
            for (;;) {
                int v = (lane == 0) ? ld_acquire_gpu(&g_pdone[layer][by][0]) : 8;
                v = __shfl_sync(0xffffffffu, v, 0);
                if (v >= 8) break;
                __nanosleep(128);
            }
            by_ready = by + 1;
        }
        const size_t off = (size_t)t * BH + outbase;
        float xv = __ldcg(&xw[off]);

        if (t > 0) {
            for (;;) {
                int v = (lane < 2) ? ld_acquire_gpu(pf) : 0x7fffffff;
                if (__all_sync(0xffffffffu, v >= t)) break;
            }
            const float4* src = reinterpret_cast<const float4*>(
                hbuf + (size_t)(t - 1) * BH + (size_t)rowbase * Hdim);
            #pragma unroll
            for (int i = 0; i < 4; i++)
                hs4[l_b[i] * 128 + w * 16 + l_q[i]] =
                    __ldcg(&src[l_b[i] * 128 + w * 16 + l_q[i]]);
        } else {
            float4 z = make_float4(0.f, 0.f, 0.f, 0.f);
            #pragma unroll
            for (int i = 0; i < 4; i++)
                hs4[l_b[i] * 128 + w * 16 + l_q[i]] = z;
        }
        __syncwarp();

        float acc[8];
        #pragma unroll
        for (int b = 0; b < 8; b++) acc[b] = 0.f;
        #pragma unroll
        for (int i = 0; i < 16; i++) {
            float4 w4 = wv[i];
            #pragma unroll
            for (int b = 0; b < 8; b++) {
                float4 h4 = hs4[b * 128 + w * 16 + i];
                acc[b] = fmaf(h4.w, w4.w,
                          fmaf(h4.z, w4.z,
                           fmaf(h4.y, w4.y,
                            fmaf(h4.x, w4.x, acc[b]))));
            }
        }
        #pragma unroll
        for (int b = 0; b < 8; b++)
            part[(w * 8 + b) * 32 + lane] = acc[b];
        __syncthreads();

        {
            float s2 = 0.f;
            #pragma unroll
            for (int ww = 0; ww < 8; ww++)
                s2 += part[(ww * 8 + b2) * 32 + j2];
            hbuf[off] = fmaxf(xv + s2, 0.f);
        }
        __syncthreads();
        if (tid == 0) st_release_gpu(myflag, t + 1);
    }
}

// ---------------------------------------------------------------------------
// FC + sigmoid: out[b*T + t] = sigmoid(dot(h1[t][b], W_fc) + b_fc)
// ---------------------------------------------------------------------------
__global__ __launch_bounds__(256) void fc_sigmoid(
    const float* __restrict__ wfc, const float* __restrict__ bfc,
    float* __restrict__ out)
{
    int gw   = (blockIdx.x * blockDim.x + threadIdx.x) >> 5;
    int lane = threadIdx.x & 31;
    int t = gw >> 6, b = gw & 63;

    const float4* hp = reinterpret_cast<const float4*>(g_h1 + (size_t)gw * Hdim);
    const float4* wp = reinterpret_cast<const float4*>(wfc);
    float s = 0.f;
    #pragma unroll
    for (int r = 0; r < 4; r++) {
        float4 hv = hp[lane + r * 32];
        float4 wv = wp[lane + r * 32];
        s += hv.x * wv.x + hv.y * wv.y + hv.z * wv.z + hv.w * wv.w;
    }
    #pragma unroll
    for (int o = 16; o > 0; o >>= 1)
        s += __shfl_xor_sync(0xffffffffu, s, o);
    if (lane == 0) {
        float v = s + bfc[0];
        out[(size_t)b * Tdim + t] = 1.f / (1.f + expf(-v));
    }
}

// ---------------------------------------------------------------------------
extern "C" void kernel_launch(void* const* d_in, const int* in_sizes, int n_in,
                              void* d_out, int out_size)
{
    (void)in_sizes; (void)n_in; (void)out_size;
    const float* x    = (const float*)d_in[0];
    const float* Wih0 = (const float*)d_in[1];
    const float* Whh0 = (const float*)d_in[2];
    const float* bih0 = (const float*)d_in[3];
    const float* bhh0 = (const float*)d_in[4];
    const float* Wih1 = (const float*)d_in[5];
    const float* Whh1 = (const float*)d_in[6];
    const float* bih1 = (const float*)d_in[7];
    const float* bhh1 = (const float*)d_in[8];
    const float* Wfc  = (const float*)d_in[9];
    const float* bfc  = (const float*)d_in[10];
    float* out = (float*)d_out;

    const int dyn_smem = TOT_FL * sizeof(float);  // 110592 B
    static bool attr_set = false;
    if (!attr_set) {
        cudaFuncSetAttribute(proj_tc<Idim, true>,
                             cudaFuncAttributeMaxDynamicSharedMemorySize, dyn_smem);
        cudaFuncSetAttribute(proj_tc<Hdim, false>,
                             cudaFuncAttributeMaxDynamicSharedMemorySize, dyn_smem);
        attr_set = true;
    }

    dim3 gemm_grid(8, 256);
    dim3 scan_grid(16, 8);

    cudaLaunchAttribute pdl_at[1];
    pdl_at[0].id = cudaLaunchAttributeProgrammaticStreamSerialization;
    pdl_at[0].val.programmaticStreamSerializationAllowed = 1;

    // Probe PDL support once (zero kernel as harmless successor).
    static int pdl_ok = -1;
    bool zero_done = false;
    if (pdl_ok != 0) {
        cudaLaunchConfig_t zc = {};
        zc.gridDim = dim3(32, 1, 1);
        zc.blockDim = dim3(512, 1, 1);
        zc.dynamicSmemBytes = 0;
        zc.stream = 0;
        zc.attrs = pdl_at;
        zc.numAttrs = 1;
        cudaError_t e = cudaLaunchKernelEx(&zc, zero_flags_k);
        if (e == cudaSuccess) { pdl_ok = 1; zero_done = true; }
        else { (void)cudaGetLastError(); pdl_ok = 0; }
    }
    if (!zero_done) zero_flags_k<<<32, 512>>>();

    if (pdl_ok == 1) {
        // Forward-dep chain (no kernel waits on a later launch):
        //   proj0 (plain, triggers at entry, never waits)
        //   scan0 (PDL successor: mounts as proj0 retires; gates on pdone[0])
        //   proj1 (PDL successor of scan0: R12-proven overlap; gates on flags)
        //   scan1 (plain: starts at proj1 completion; gates pass instantly)
        proj_tc<Idim, true><<<gemm_grid, 256, dyn_smem>>>(x, Wih0, bih0, bhh0);

        cudaLaunchConfig_t sc = {};
        sc.gridDim = scan_grid;
        sc.blockDim = dim3(256, 1, 1);
        sc.dynamicSmemBytes = 0;
        sc.stream = 0;
        sc.attrs = pdl_at;
        sc.numAttrs = 1;
        cudaLaunchKernelEx(&sc, rnn_scan, Whh0, 0);

        cudaLaunchConfig_t pc = {};
        pc.gridDim = gemm_grid;
        pc.blockDim = dim3(256, 1, 1);
        pc.dynamicSmemBytes = dyn_smem;
        pc.stream = 0;
        pc.attrs = pdl_at;
        pc.numAttrs = 1;
        cudaLaunchKernelEx(&pc, proj_tc<Hdim, false>, x, Wih1, bih1, bhh1);

        rnn_scan<<<scan_grid, 256>>>(Whh1, 1);
    } else {
        // Safe serial order: every gate passes instantly.
        proj_tc<Idim, true><<<gemm_grid, 256, dyn_smem>>>(x, Wih0, bih0, bhh0);
        rnn_scan<<<scan_grid, 256>>>(Whh0, 0);
        proj_tc<Hdim, false><<<gemm_grid, 256, dyn_smem>>>(x, Wih1, bih1, bhh1);
        rnn_scan<<<scan_grid, 256>>>(Whh1, 1);
    }

    // Head
    fc_sigmoid<<<4096, 256>>>(Wfc, bfc, out);
}